// round 1
// baseline (speedup 1.0000x reference)
#include <cuda_runtime.h>
#include <math.h>

// Problem constants (B=2, S=4096 -> N=8192 tokens)
#define NTOK 8192
#define DDIM 2048
#define ENUM 8
#define FDIM 8192

// ---------------------------------------------------------------------------
// Device scratch (no allocations allowed -> __device__ globals)
// ---------------------------------------------------------------------------
__device__ float g_logits[NTOK * ENUM];          // [N, E] router logits
__device__ float g_sums[ENUM];                   // per-expert logit sums
__device__ int   g_sel[2];                       // top-2 expert indices
__device__ float g_rw[NTOK * 2];                 // per-token softmax weights
__device__ float g_h[(size_t)2 * NTOK * FDIM];   // [2, N, F] hidden acts (512 MB)

// ---------------------------------------------------------------------------
// GELU (tanh approximation == jax.nn.gelu default)
// ---------------------------------------------------------------------------
__device__ __forceinline__ float gelu_tanh(float v) {
    const float c0 = 0.7978845608028654f;   // sqrt(2/pi)
    const float c1 = 0.044715f;
    float v3 = v * v * v;
    float t = tanhf(c0 * (v + c1 * v3));
    return 0.5f * v * (1.0f + t);
}

// ---------------------------------------------------------------------------
// Router: logits[n][e] = dot(x[n], gate_w[e]); one warp per token
// ---------------------------------------------------------------------------
__global__ void router_kernel(const float* __restrict__ x,
                              const float* __restrict__ gw) {
    int warp = threadIdx.x >> 5;
    int lane = threadIdx.x & 31;
    int n = blockIdx.x * 8 + warp;
    if (n >= NTOK) return;

    const float4* xr = (const float4*)(x + (size_t)n * DDIM);
    float acc[ENUM];
#pragma unroll
    for (int e = 0; e < ENUM; e++) acc[e] = 0.0f;

    for (int i = lane; i < DDIM / 4; i += 32) {
        float4 xv = xr[i];
#pragma unroll
        for (int e = 0; e < ENUM; e++) {
            float4 gv = ((const float4*)(gw + (size_t)e * DDIM))[i];
            acc[e] += xv.x * gv.x + xv.y * gv.y + xv.z * gv.z + xv.w * gv.w;
        }
    }
#pragma unroll
    for (int e = 0; e < ENUM; e++) {
#pragma unroll
        for (int off = 16; off > 0; off >>= 1)
            acc[e] += __shfl_down_sync(0xFFFFFFFFu, acc[e], off);
    }
    if (lane == 0) {
#pragma unroll
        for (int e = 0; e < ENUM; e++)
            g_logits[(size_t)n * ENUM + e] = acc[e];
    }
}

// ---------------------------------------------------------------------------
// Deterministic per-expert column sum (fixed partition + fixed tree)
// ---------------------------------------------------------------------------
__global__ void colsum_kernel() {
    __shared__ float s[256];
    int e = blockIdx.x;
    float a = 0.0f;
    for (int n = threadIdx.x; n < NTOK; n += 256)
        a += g_logits[(size_t)n * ENUM + e];
    s[threadIdx.x] = a;
    __syncthreads();
    for (int stride = 128; stride > 0; stride >>= 1) {
        if (threadIdx.x < stride) s[threadIdx.x] += s[threadIdx.x + stride];
        __syncthreads();
    }
    if (threadIdx.x == 0) g_sums[e] = s[0];
}

// ---------------------------------------------------------------------------
// Top-2 select (stable descending: ties -> lower index, matches lax.top_k)
// ---------------------------------------------------------------------------
__global__ void select_kernel() {
    if (threadIdx.x != 0 || blockIdx.x != 0) return;
    float v0 = -INFINITY, v1 = -INFINITY;
    int b0 = 0, b1 = 0;
    for (int e = 0; e < ENUM; e++) {
        float v = g_sums[e];
        if (v > v0) { v1 = v0; b1 = b0; v0 = v; b0 = e; }
        else if (v > v1) { v1 = v; b1 = e; }
    }
    g_sel[0] = b0;
    g_sel[1] = b1;
}

// ---------------------------------------------------------------------------
// Per-token softmax over the two selected experts' logits
// ---------------------------------------------------------------------------
__global__ void rw_kernel() {
    int n = blockIdx.x * blockDim.x + threadIdx.x;
    if (n >= NTOK) return;
    int s0 = g_sel[0], s1 = g_sel[1];
    float l0 = g_logits[(size_t)n * ENUM + s0];
    float l1 = g_logits[(size_t)n * ENUM + s1];
    float m = fmaxf(l0, l1);
    float e0 = expf(l0 - m);
    float e1 = expf(l1 - m);
    float inv = 1.0f / (e0 + e1);
    g_rw[2 * n + 0] = e0 * inv;
    g_rw[2 * n + 1] = e1 * inv;
}

// ---------------------------------------------------------------------------
// 128x128x8 tiled SGEMM, 8x8 per-thread micro-tile, 256 threads.
//   C[M,N] = A[M,K] @ B[K,N] + bias[N]   (B/bias selected by g_sel[kslot])
// MODE 0: C = gelu(acc + bias)                (GEMM1 -> g_h)
// MODE 1: C = rw[n][kslot] * (acc + bias)     (GEMM2 expert slot 0, write)
// MODE 2: C += rw[n][kslot] * (acc + bias)    (GEMM2 expert slot 1, accumulate)
// All dims are multiples of the tile sizes -> no bounds checks.
// ---------------------------------------------------------------------------
template <int MODE>
__global__ void __launch_bounds__(256, 2)
gemm128(const float* __restrict__ A, const float* __restrict__ Bbase,
        const float* __restrict__ biasBase, float* __restrict__ C,
        int M, int N, int K, int kslot) {
    const int BM = 128, BN = 128, BK = 8, TM = 8, TN = 8;
    __shared__ float As[BK][BM];
    __shared__ float Bs[BK][BN];

    int tid = threadIdx.x;
    int sel = g_sel[kslot];
    const float* Bp = Bbase + (size_t)sel * K * N + blockIdx.x * BN;
    const float* bias = biasBase + (size_t)sel * N;
    const float* Ap = A + (size_t)blockIdx.y * BM * K;

    int aRow = tid >> 1;          // 0..127
    int aCol = (tid & 1) * 4;     // 0 or 4
    int bRow = tid >> 5;          // 0..7
    int bCol = (tid & 31) * 4;    // 0..124

    int tRow = (tid >> 4) * TM;   // 0..120
    int tCol = (tid & 15) * TN;   // 0..120

    float acc[TM][TN];
#pragma unroll
    for (int i = 0; i < TM; i++)
#pragma unroll
        for (int j = 0; j < TN; j++) acc[i][j] = 0.0f;

    for (int k0 = 0; k0 < K; k0 += BK) {
        float4 av = *(const float4*)(Ap + (size_t)aRow * K + k0 + aCol);
        As[aCol + 0][aRow] = av.x;
        As[aCol + 1][aRow] = av.y;
        As[aCol + 2][aRow] = av.z;
        As[aCol + 3][aRow] = av.w;
        *(float4*)&Bs[bRow][bCol] =
            *(const float4*)(Bp + (size_t)(k0 + bRow) * N + bCol);
        __syncthreads();

#pragma unroll
        for (int kk = 0; kk < BK; kk++) {
            float regM[TM], regN[TN];
            *(float4*)(regM + 0) = *(const float4*)&As[kk][tRow];
            *(float4*)(regM + 4) = *(const float4*)&As[kk][tRow + 4];
            *(float4*)(regN + 0) = *(const float4*)&Bs[kk][tCol];
            *(float4*)(regN + 4) = *(const float4*)&Bs[kk][tCol + 4];
#pragma unroll
            for (int i = 0; i < TM; i++)
#pragma unroll
                for (int j = 0; j < TN; j++)
                    acc[i][j] = fmaf(regM[i], regN[j], acc[i][j]);
        }
        __syncthreads();
    }

    int cn = blockIdx.x * BN + tCol;
#pragma unroll
    for (int i = 0; i < TM; i++) {
        size_t r = (size_t)blockIdx.y * BM + tRow + i;
        float* Crow = C + r * N + cn;
        float w = (MODE == 0) ? 0.0f : g_rw[r * 2 + kslot];
#pragma unroll
        for (int j = 0; j < TN; j++) {
            float v = acc[i][j] + bias[cn + j];
            if (MODE == 0)      Crow[j] = gelu_tanh(v);
            else if (MODE == 1) Crow[j] = w * v;
            else                Crow[j] += w * v;
        }
    }
}

// ---------------------------------------------------------------------------
// Launch
// ---------------------------------------------------------------------------
extern "C" void kernel_launch(void* const* d_in, const int* in_sizes, int n_in,
                              void* d_out, int out_size) {
    (void)in_sizes; (void)n_in; (void)out_size;
    const float* x  = (const float*)d_in[0];  // [2,4096,2048]
    const float* gw = (const float*)d_in[1];  // [8,2048]
    const float* w1 = (const float*)d_in[2];  // [8,2048,8192]
    const float* b1 = (const float*)d_in[3];  // [8,8192]
    const float* w2 = (const float*)d_in[4];  // [8,8192,2048]
    const float* b2 = (const float*)d_in[5];  // [8,2048]
    float* out = (float*)d_out;               // [2,4096,2048]

    void* hsym = nullptr;
    cudaGetSymbolAddress(&hsym, g_h);
    float* h = (float*)hsym;

    // Routing
    router_kernel<<<NTOK / 8, 256>>>(x, gw);
    colsum_kernel<<<ENUM, 256>>>();
    select_kernel<<<1, 1>>>();
    rw_kernel<<<NTOK / 256, 256>>>();

    // GEMM1: h[k] = gelu(x @ w1[sel_k] + b1[sel_k])   [8192, 8192], K=2048
    dim3 g1(FDIM / 128, NTOK / 128);
    gemm128<0><<<g1, 256>>>(x, w1, b1, h,                       NTOK, FDIM, DDIM, 0);
    gemm128<0><<<g1, 256>>>(x, w1, b1, h + (size_t)NTOK * FDIM, NTOK, FDIM, DDIM, 1);

    // GEMM2 + weighted combine: out = sum_k rw[:,k] * (h[k] @ w2[sel_k] + b2[sel_k])
    dim3 g2(DDIM / 128, NTOK / 128);
    gemm128<1><<<g2, 256>>>(h,                       w2, b2, out, NTOK, DDIM, FDIM, 0);
    gemm128<2><<<g2, 256>>>(h + (size_t)NTOK * FDIM, w2, b2, out, NTOK, DDIM, FDIM, 1);
}

// round 2
// speedup vs baseline: 2.6565x; 2.6565x over previous
#include <cuda_runtime.h>
#include <math.h>
#include <stdint.h>

// Problem constants (B=2, S=4096 -> N=8192 tokens)
#define NTOK 8192
#define DDIM 2048
#define ENUM 8
#define FDIM 8192

// ---------------------------------------------------------------------------
// Device scratch (no allocations allowed -> __device__ globals)
// ---------------------------------------------------------------------------
__device__ float g_logits[NTOK * ENUM];          // [N, E] router logits
__device__ float g_sums[ENUM];                   // per-expert logit sums
__device__ int   g_sel[2];                       // top-2 expert indices
__device__ float g_rw[NTOK * 2];                 // per-token softmax weights
__device__ float g_h[(size_t)2 * NTOK * FDIM];   // [2, N, F] hidden (tf32-rounded)
__device__ float g_xr[(size_t)NTOK * DDIM];      // x rounded to tf32
__device__ float g_w1r[(size_t)2 * DDIM * FDIM]; // selected w1 slices, tf32-rounded
__device__ float g_w2r[(size_t)2 * FDIM * DDIM]; // selected w2 slices, tf32-rounded

// ---------------------------------------------------------------------------
// Helpers
// ---------------------------------------------------------------------------
__device__ __forceinline__ float to_tf32(float x) {
    uint32_t u;
    asm("cvt.rna.tf32.f32 %0, %1;" : "=r"(u) : "f"(x));
    return __uint_as_float(u);
}

__device__ __forceinline__ float gelu_tanh(float v) {
    const float c0 = 0.7978845608028654f;   // sqrt(2/pi)
    const float c1 = 0.044715f;
    float v3 = v * v * v;
    float t = tanhf(c0 * (v + c1 * v3));
    return 0.5f * v * (1.0f + t);
}

__device__ __forceinline__ void mma_tf32(float (&c)[4], const uint32_t (&a)[4],
                                         const uint32_t (&b)[2]) {
    asm volatile(
        "mma.sync.aligned.m16n8k8.row.col.f32.tf32.tf32.f32 "
        "{%0,%1,%2,%3}, {%4,%5,%6,%7}, {%8,%9}, {%0,%1,%2,%3};"
        : "+f"(c[0]), "+f"(c[1]), "+f"(c[2]), "+f"(c[3])
        : "r"(a[0]), "r"(a[1]), "r"(a[2]), "r"(a[3]), "r"(b[0]), "r"(b[1]));
}

// ---------------------------------------------------------------------------
// Router: logits[n][e] = dot(x[n], gate_w[e]); one warp per token (fp32 exact)
// ---------------------------------------------------------------------------
__global__ void router_kernel(const float* __restrict__ x,
                              const float* __restrict__ gw) {
    int warp = threadIdx.x >> 5;
    int lane = threadIdx.x & 31;
    int n = blockIdx.x * 8 + warp;
    if (n >= NTOK) return;

    const float4* xr = (const float4*)(x + (size_t)n * DDIM);
    float acc[ENUM];
#pragma unroll
    for (int e = 0; e < ENUM; e++) acc[e] = 0.0f;

    for (int i = lane; i < DDIM / 4; i += 32) {
        float4 xv = xr[i];
#pragma unroll
        for (int e = 0; e < ENUM; e++) {
            float4 gv = ((const float4*)(gw + (size_t)e * DDIM))[i];
            acc[e] += xv.x * gv.x + xv.y * gv.y + xv.z * gv.z + xv.w * gv.w;
        }
    }
#pragma unroll
    for (int e = 0; e < ENUM; e++) {
#pragma unroll
        for (int off = 16; off > 0; off >>= 1)
            acc[e] += __shfl_down_sync(0xFFFFFFFFu, acc[e], off);
    }
    if (lane == 0) {
#pragma unroll
        for (int e = 0; e < ENUM; e++)
            g_logits[(size_t)n * ENUM + e] = acc[e];
    }
}

// Deterministic per-expert column sum (fixed partition + fixed tree)
__global__ void colsum_kernel() {
    __shared__ float s[256];
    int e = blockIdx.x;
    float a = 0.0f;
    for (int n = threadIdx.x; n < NTOK; n += 256)
        a += g_logits[(size_t)n * ENUM + e];
    s[threadIdx.x] = a;
    __syncthreads();
    for (int stride = 128; stride > 0; stride >>= 1) {
        if (threadIdx.x < stride) s[threadIdx.x] += s[threadIdx.x + stride];
        __syncthreads();
    }
    if (threadIdx.x == 0) g_sums[e] = s[0];
}

// Top-2 select (stable descending: ties -> lower index, matches lax.top_k)
__global__ void select_kernel() {
    if (threadIdx.x != 0 || blockIdx.x != 0) return;
    float v0 = -INFINITY, v1 = -INFINITY;
    int b0 = 0, b1 = 0;
    for (int e = 0; e < ENUM; e++) {
        float v = g_sums[e];
        if (v > v0) { v1 = v0; b1 = b0; v0 = v; b0 = e; }
        else if (v > v1) { v1 = v; b1 = e; }
    }
    g_sel[0] = b0;
    g_sel[1] = b1;
}

// Per-token softmax over the two selected experts' logits
__global__ void rw_kernel() {
    int n = blockIdx.x * blockDim.x + threadIdx.x;
    if (n >= NTOK) return;
    int s0 = g_sel[0], s1 = g_sel[1];
    float l0 = g_logits[(size_t)n * ENUM + s0];
    float l1 = g_logits[(size_t)n * ENUM + s1];
    float m = fmaxf(l0, l1);
    float e0 = expf(l0 - m);
    float e1 = expf(l1 - m);
    float inv = 1.0f / (e0 + e1);
    g_rw[2 * n + 0] = e0 * inv;
    g_rw[2 * n + 1] = e1 * inv;
}

// ---------------------------------------------------------------------------
// tf32 rounding pre-passes (round-to-nearest; avoids HW truncation bias)
// ---------------------------------------------------------------------------
__global__ void round_copy(const float* __restrict__ src, float* __restrict__ dst,
                           int n4) {
    int i = blockIdx.x * blockDim.x + threadIdx.x;
    if (i >= n4) return;
    float4 v = ((const float4*)src)[i];
    v.x = to_tf32(v.x); v.y = to_tf32(v.y);
    v.z = to_tf32(v.z); v.w = to_tf32(v.w);
    ((float4*)dst)[i] = v;
}

// Gathers the selected expert's slice (sel read on device) + rounds to tf32.
__global__ void round_expert(const float* __restrict__ base, float* __restrict__ dst,
                             size_t per_expert, int kslot, int n4) {
    int i = blockIdx.x * blockDim.x + threadIdx.x;
    if (i >= n4) return;
    const float4* src = (const float4*)(base + (size_t)g_sel[kslot] * per_expert);
    float4 v = src[i];
    v.x = to_tf32(v.x); v.y = to_tf32(v.y);
    v.z = to_tf32(v.z); v.w = to_tf32(v.w);
    ((float4*)dst)[i] = v;
}

// ---------------------------------------------------------------------------
// tf32 tensor-core GEMM: 128x128x32 block tile, 8 warps, warp tile 64x32,
// m16n8k8 fragments (4x4 per warp), double-buffered cp.async.
//   C[M,N] = A[M,K] @ B[K,N] (+bias/gelu/weighted per MODE)
// A, B must be pre-rounded to tf32 values stored as fp32.
// MODE 0: C = to_tf32(gelu(acc + bias))       (GEMM1 -> g_h, pre-rounded for GEMM2)
// MODE 1: C = rw[n][kslot] * (acc + bias)     (GEMM2 slot 0, write)
// MODE 2: C += rw[n][kslot] * (acc + bias)    (GEMM2 slot 1, accumulate)
// ---------------------------------------------------------------------------
#define BM 128
#define BN 128
#define BKT 32
#define SA 36                       // As[m][k] row stride (floats): frag lds conflict-free
#define SB 136                      // Bs[k][n] row stride (floats): frag lds conflict-free
#define ASZ (BM * SA)               // 4608 floats / stage
#define BSZ (BKT * SB)              // 4352 floats / stage
#define GEMM_SMEM ((2 * ASZ + 2 * BSZ) * 4)   // 71680 bytes

template <int MODE>
__global__ void __launch_bounds__(256, 2)
gemm_tf32(const float* __restrict__ A, const float* __restrict__ B,
          const float* __restrict__ biasBase, float* __restrict__ C,
          int M, int N, int K, int kslot) {
    extern __shared__ float smem[];
    float* As = smem;               // [2][BM][SA]
    float* Bs = smem + 2 * ASZ;     // [2][BKT][SB]

    const int tid = threadIdx.x;
    const int lane = tid & 31;
    const int warp = tid >> 5;
    const int mW = (warp >> 2) * 64;   // warp m-offset (2 rows of warps)
    const int nW = (warp & 3) * 32;    // warp n-offset (4 cols of warps)

    const int sel = g_sel[kslot];
    const float* Ap = A + (size_t)blockIdx.y * BM * K;
    const float* Bp = B + (size_t)blockIdx.x * BN;
    const float* bias = biasBase + (size_t)sel * N;

    float acc[4][4][4];
#pragma unroll
    for (int mf = 0; mf < 4; mf++)
#pragma unroll
        for (int nf = 0; nf < 4; nf++)
#pragma unroll
            for (int i = 0; i < 4; i++) acc[mf][nf][i] = 0.0f;

    const int NT = K / BKT;

    // --- async stage loader ---
    auto issue = [&](int kt, int buf) {
        const float* Asrc = Ap + (size_t)kt * BKT;
        const float* Bsrc = Bp + (size_t)kt * BKT * N;
        float* Asm = As + buf * ASZ;
        float* Bsm = Bs + buf * BSZ;
#pragma unroll
        for (int i = 0; i < 4; i++) {
            int idx = tid + 256 * i;
            int m = idx >> 3, kq = (idx & 7) * 4;      // coalesced: 4 rows x 128B / warp
            uint32_t d = (uint32_t)__cvta_generic_to_shared(Asm + m * SA + kq);
            asm volatile("cp.async.cg.shared.global [%0], [%1], 16;"
                         :: "r"(d), "l"(Asrc + (size_t)m * K + kq));
        }
#pragma unroll
        for (int i = 0; i < 4; i++) {
            int idx = tid + 256 * i;
            int k = idx >> 5, n = (idx & 31) * 4;      // coalesced: full 512B rows
            uint32_t d = (uint32_t)__cvta_generic_to_shared(Bsm + k * SB + n);
            asm volatile("cp.async.cg.shared.global [%0], [%1], 16;"
                         :: "r"(d), "l"(Bsrc + (size_t)k * N + n));
        }
        asm volatile("cp.async.commit_group;");
    };

    issue(0, 0);

    for (int kt = 0; kt < NT; kt++) {
        if (kt + 1 < NT) {
            issue(kt + 1, (kt + 1) & 1);
            asm volatile("cp.async.wait_group 1;" ::: "memory");
        } else {
            asm volatile("cp.async.wait_group 0;" ::: "memory");
        }
        __syncthreads();

        const float* Asb = As + (kt & 1) * ASZ;
        const float* Bsb = Bs + (kt & 1) * BSZ;

#pragma unroll
        for (int ks = 0; ks < 4; ks++) {            // 4 x k8 steps per BK=32
            uint32_t af[4][4];
            uint32_t bf[4][2];
            const int arow = mW + (lane >> 2);
            const int acol = ks * 8 + (lane & 3);
#pragma unroll
            for (int mf = 0; mf < 4; mf++) {
                const float* p = Asb + (size_t)(arow + mf * 16) * SA + acol;
                af[mf][0] = __float_as_uint(p[0]);
                af[mf][1] = __float_as_uint(p[8 * SA]);
                af[mf][2] = __float_as_uint(p[4]);
                af[mf][3] = __float_as_uint(p[8 * SA + 4]);
            }
            const int brow = ks * 8 + (lane & 3);
            const int bcol = nW + (lane >> 2);
#pragma unroll
            for (int nf = 0; nf < 4; nf++) {
                const float* p = Bsb + (size_t)brow * SB + bcol + nf * 8;
                bf[nf][0] = __float_as_uint(p[0]);
                bf[nf][1] = __float_as_uint(p[4 * SB]);
            }
#pragma unroll
            for (int mf = 0; mf < 4; mf++)
#pragma unroll
                for (int nf = 0; nf < 4; nf++)
                    mma_tf32(acc[mf][nf], af[mf], bf[nf]);
        }
        __syncthreads();
    }

    // --- epilogue ---
    const int bN = blockIdx.x * BN;
#pragma unroll
    for (int mf = 0; mf < 4; mf++) {
        int r0 = blockIdx.y * BM + mW + mf * 16 + (lane >> 2);
        int r1 = r0 + 8;
        float w0 = 0.0f, w1 = 0.0f;
        if (MODE != 0) {
            w0 = g_rw[r0 * 2 + kslot];
            w1 = g_rw[r1 * 2 + kslot];
        }
#pragma unroll
        for (int nf = 0; nf < 4; nf++) {
            int c0 = bN + nW + nf * 8 + (lane & 3) * 2;
            float bv0 = bias[c0], bv1 = bias[c0 + 1];
            float v00 = acc[mf][nf][0] + bv0;
            float v01 = acc[mf][nf][1] + bv1;
            float v10 = acc[mf][nf][2] + bv0;
            float v11 = acc[mf][nf][3] + bv1;
            float* p0 = C + (size_t)r0 * N + c0;
            float* p1 = C + (size_t)r1 * N + c0;
            if (MODE == 0) {
                p0[0] = to_tf32(gelu_tanh(v00));
                p0[1] = to_tf32(gelu_tanh(v01));
                p1[0] = to_tf32(gelu_tanh(v10));
                p1[1] = to_tf32(gelu_tanh(v11));
            } else if (MODE == 1) {
                p0[0] = w0 * v00;
                p0[1] = w0 * v01;
                p1[0] = w1 * v10;
                p1[1] = w1 * v11;
            } else {
                p0[0] += w0 * v00;
                p0[1] += w0 * v01;
                p1[0] += w1 * v10;
                p1[1] += w1 * v11;
            }
        }
    }
}

// ---------------------------------------------------------------------------
// Launch
// ---------------------------------------------------------------------------
extern "C" void kernel_launch(void* const* d_in, const int* in_sizes, int n_in,
                              void* d_out, int out_size) {
    (void)in_sizes; (void)n_in; (void)out_size;
    const float* x  = (const float*)d_in[0];  // [2,4096,2048]
    const float* gw = (const float*)d_in[1];  // [8,2048]
    const float* w1 = (const float*)d_in[2];  // [8,2048,8192]
    const float* b1 = (const float*)d_in[3];  // [8,8192]
    const float* w2 = (const float*)d_in[4];  // [8,8192,2048]
    const float* b2 = (const float*)d_in[5];  // [8,2048]
    float* out = (float*)d_out;               // [2,4096,2048]

    void* p;
    cudaGetSymbolAddress(&p, g_h);   float* h   = (float*)p;
    cudaGetSymbolAddress(&p, g_xr);  float* xr  = (float*)p;
    cudaGetSymbolAddress(&p, g_w1r); float* w1r = (float*)p;
    cudaGetSymbolAddress(&p, g_w2r); float* w2r = (float*)p;

    static bool attr_set = false;
    if (!attr_set) {
        cudaFuncSetAttribute(gemm_tf32<0>, cudaFuncAttributeMaxDynamicSharedMemorySize, GEMM_SMEM);
        cudaFuncSetAttribute(gemm_tf32<1>, cudaFuncAttributeMaxDynamicSharedMemorySize, GEMM_SMEM);
        cudaFuncSetAttribute(gemm_tf32<2>, cudaFuncAttributeMaxDynamicSharedMemorySize, GEMM_SMEM);
        attr_set = true;
    }

    // Routing (exact fp32; selection must match reference bit-for-bit logic)
    router_kernel<<<NTOK / 8, 256>>>(x, gw);
    colsum_kernel<<<ENUM, 256>>>();
    select_kernel<<<1, 1>>>();
    rw_kernel<<<NTOK / 256, 256>>>();

    // Round operands to tf32 (rna) once; GEMMs then consume pre-rounded data.
    const size_t perW = (size_t)DDIM * FDIM;          // elems per expert (both w1/w2)
    const int n4x = NTOK * DDIM / 4;
    const int n4w = (int)(perW / 4);
    round_copy<<<(n4x + 255) / 256, 256>>>(x, xr, n4x);
    round_expert<<<(n4w + 255) / 256, 256>>>(w1, w1r,                w2 ? perW : perW, 0, n4w);
    round_expert<<<(n4w + 255) / 256, 256>>>(w1, w1r + perW,         perW, 1, n4w);
    round_expert<<<(n4w + 255) / 256, 256>>>(w2, w2r,                perW, 0, n4w);
    round_expert<<<(n4w + 255) / 256, 256>>>(w2, w2r + perW,         perW, 1, n4w);

    // GEMM1: h[k] = to_tf32(gelu(x @ w1[sel_k] + b1[sel_k]))   M=8192 N=8192 K=2048
    dim3 g1(FDIM / BN, NTOK / BM);
    gemm_tf32<0><<<g1, 256, GEMM_SMEM>>>(xr, w1r,        b1, h,        NTOK, FDIM, DDIM, 0);
    gemm_tf32<0><<<g1, 256, GEMM_SMEM>>>(xr, w1r + perW, b1, h + (size_t)NTOK * FDIM,
                                         NTOK, FDIM, DDIM, 1);

    // GEMM2 + weighted combine: out = sum_k rw[:,k] * (h[k] @ w2[sel_k] + b2[sel_k])
    dim3 g2(DDIM / BN, NTOK / BM);
    gemm_tf32<1><<<g2, 256, GEMM_SMEM>>>(h,                        w2r,        b2, out,
                                         NTOK, DDIM, FDIM, 0);
    gemm_tf32<2><<<g2, 256, GEMM_SMEM>>>(h + (size_t)NTOK * FDIM,  w2r + perW, b2, out,
                                         NTOK, DDIM, FDIM, 1);
}

// round 7
// speedup vs baseline: 3.6549x; 1.3759x over previous
#include <cuda_runtime.h>
#include <math.h>
#include <stdint.h>

// Problem constants (B=2, S=4096 -> N=8192 tokens)
#define NTOK 8192
#define DDIM 2048
#define ENUM 8
#define FDIM 8192

// ---------------------------------------------------------------------------
// Device scratch (no allocations allowed -> __device__ globals)
// ---------------------------------------------------------------------------
__device__ float g_logits[NTOK * ENUM];          // [N, E] router logits
__device__ float g_sums[ENUM];                   // per-expert logit sums
__device__ int   g_sel[2];                       // top-2 expert indices
__device__ float g_rw[NTOK * 2];                 // per-token softmax weights
__device__ float g_h[(size_t)NTOK * 2 * FDIM];   // [N, 2F]: rw-scaled hidden, tf32
__device__ float g_xr[(size_t)NTOK * DDIM];      // x rounded to tf32
__device__ float g_w1r[(size_t)2 * DDIM * FDIM]; // selected w1 slices, tf32
__device__ float g_w2r[(size_t)2 * FDIM * DDIM]; // selected w2 slices, tf32 ([2F, D])

// ---------------------------------------------------------------------------
// Helpers
// ---------------------------------------------------------------------------
__device__ __forceinline__ float to_tf32(float x) {
    uint32_t u;
    asm("cvt.rna.tf32.f32 %0, %1;" : "=r"(u) : "f"(x));
    return __uint_as_float(u);
}

__device__ __forceinline__ float gelu_tanh(float v) {
    const float c0 = 0.7978845608028654f;   // sqrt(2/pi)
    const float c1 = 0.044715f;
    float v3 = v * v * v;
    float t = tanhf(c0 * (v + c1 * v3));
    return 0.5f * v * (1.0f + t);
}

__device__ __forceinline__ void mma_tf32(float (&c)[4], const uint32_t (&a)[4],
                                         const uint32_t (&b)[2]) {
    asm volatile(
        "mma.sync.aligned.m16n8k8.row.col.f32.tf32.tf32.f32 "
        "{%0,%1,%2,%3}, {%4,%5,%6,%7}, {%8,%9}, {%0,%1,%2,%3};"
        : "+f"(c[0]), "+f"(c[1]), "+f"(c[2]), "+f"(c[3])
        : "r"(a[0]), "r"(a[1]), "r"(a[2]), "r"(a[3]), "r"(b[0]), "r"(b[1]));
}

// ---------------------------------------------------------------------------
// Router: logits[n][e] = dot(x[n], gate_w[e]); one warp per token (fp32 exact)
// ---------------------------------------------------------------------------
__global__ void router_kernel(const float* __restrict__ x,
                              const float* __restrict__ gw) {
    int warp = threadIdx.x >> 5;
    int lane = threadIdx.x & 31;
    int n = blockIdx.x * 8 + warp;
    if (n >= NTOK) return;

    const float4* xr = (const float4*)(x + (size_t)n * DDIM);
    float acc[ENUM];
#pragma unroll
    for (int e = 0; e < ENUM; e++) acc[e] = 0.0f;

    for (int i = lane; i < DDIM / 4; i += 32) {
        float4 xv = xr[i];
#pragma unroll
        for (int e = 0; e < ENUM; e++) {
            float4 gv = ((const float4*)(gw + (size_t)e * DDIM))[i];
            acc[e] += xv.x * gv.x + xv.y * gv.y + xv.z * gv.z + xv.w * gv.w;
        }
    }
#pragma unroll
    for (int e = 0; e < ENUM; e++) {
#pragma unroll
        for (int off = 16; off > 0; off >>= 1)
            acc[e] += __shfl_down_sync(0xFFFFFFFFu, acc[e], off);
    }
    if (lane == 0) {
#pragma unroll
        for (int e = 0; e < ENUM; e++)
            g_logits[(size_t)n * ENUM + e] = acc[e];
    }
}

// Deterministic per-expert column sum (fixed partition + fixed tree)
__global__ void colsum_kernel() {
    __shared__ float s[256];
    int e = blockIdx.x;
    float a = 0.0f;
    for (int n = threadIdx.x; n < NTOK; n += 256)
        a += g_logits[(size_t)n * ENUM + e];
    s[threadIdx.x] = a;
    __syncthreads();
    for (int stride = 128; stride > 0; stride >>= 1) {
        if (threadIdx.x < stride) s[threadIdx.x] += s[threadIdx.x + stride];
        __syncthreads();
    }
    if (threadIdx.x == 0) g_sums[e] = s[0];
}

// Top-2 select (stable descending: ties -> lower index, matches lax.top_k)
__global__ void select_kernel() {
    if (threadIdx.x != 0 || blockIdx.x != 0) return;
    float v0 = -INFINITY, v1 = -INFINITY;
    int b0 = 0, b1 = 0;
    for (int e = 0; e < ENUM; e++) {
        float v = g_sums[e];
        if (v > v0) { v1 = v0; b1 = b0; v0 = v; b0 = e; }
        else if (v > v1) { v1 = v; b1 = e; }
    }
    g_sel[0] = b0;
    g_sel[1] = b1;
}

// Per-token softmax over the two selected experts' logits
__global__ void rw_kernel() {
    int n = blockIdx.x * blockDim.x + threadIdx.x;
    if (n >= NTOK) return;
    int s0 = g_sel[0], s1 = g_sel[1];
    float l0 = g_logits[(size_t)n * ENUM + s0];
    float l1 = g_logits[(size_t)n * ENUM + s1];
    float m = fmaxf(l0, l1);
    float e0 = expf(l0 - m);
    float e1 = expf(l1 - m);
    float inv = 1.0f / (e0 + e1);
    g_rw[2 * n + 0] = e0 * inv;
    g_rw[2 * n + 1] = e1 * inv;
}

// ---------------------------------------------------------------------------
// tf32 rounding pre-passes (round-to-nearest; avoids HW truncation bias)
// ---------------------------------------------------------------------------
__global__ void round_copy(const float* __restrict__ src, float* __restrict__ dst,
                           int n4) {
    int i = blockIdx.x * blockDim.x + threadIdx.x;
    if (i >= n4) return;
    float4 v = ((const float4*)src)[i];
    v.x = to_tf32(v.x); v.y = to_tf32(v.y);
    v.z = to_tf32(v.z); v.w = to_tf32(v.w);
    ((float4*)dst)[i] = v;
}

// Gathers the selected expert's slice (sel read on device) + rounds to tf32.
__global__ void round_expert(const float* __restrict__ base, float* __restrict__ dst,
                             size_t per_expert, int kslot, int n4) {
    int i = blockIdx.x * blockDim.x + threadIdx.x;
    if (i >= n4) return;
    const float4* src = (const float4*)(base + (size_t)g_sel[kslot] * per_expert);
    float4 v = src[i];
    v.x = to_tf32(v.x); v.y = to_tf32(v.y);
    v.z = to_tf32(v.z); v.w = to_tf32(v.w);
    ((float4*)dst)[i] = v;
}

// ---------------------------------------------------------------------------
// tf32 tensor-core GEMM: 256x128x32 block tile, 8 warps (4x2), warp 64x64,
// m16n8k8 frags (4x8 per warp), 3-stage cp.async pipeline.
//   C = A[M,K] @ B[K,N]   (A,B pre-rounded to tf32)
// MODE 0 (GEMM1): C[r, c] = to_tf32( rw[r][kslot] * gelu(acc + b1[sel][c]) )
//                 C pre-offset to h + kslot*FDIM, ldc = 2*FDIM
// MODE 1 (GEMM2): C[r, c] = acc + rw[r][0]*b2[s0][c] + rw[r][1]*b2[s1][c]
// ---------------------------------------------------------------------------
#define BM 256
#define BN 128
#define BKT 32
#define SA 36                       // As[m][k] stride (floats), conflict-free frags
#define SB 136                      // Bs[k][n] stride (floats), conflict-free frags
#define ASZ (BM * SA)               // 9216 floats / stage
#define BSZ (BKT * SB)              // 4352 floats / stage
#define STAGES 3
#define GEMM_SMEM ((ASZ + BSZ) * STAGES * 4)   // 162816 bytes

template <int MODE>
__global__ void __launch_bounds__(256, 1)
gemm_tf32(const float* __restrict__ A, const float* __restrict__ B,
          const float* __restrict__ b1v, const float* __restrict__ b2v,
          float* __restrict__ C, int N, int K, int ldc, int kslot) {
    extern __shared__ float smem[];

    const int tid = threadIdx.x;
    const int lane = tid & 31;
    const int warp = tid >> 5;
    const int mW = (warp >> 1) * 64;   // 4 warp-rows
    const int nW = (warp & 1) * 64;    // 2 warp-cols

    const float* Ap = A + (size_t)blockIdx.y * BM * K;
    const float* Bp = B + (size_t)blockIdx.x * BN;

    float acc[4][8][4];
#pragma unroll
    for (int mf = 0; mf < 4; mf++)
#pragma unroll
        for (int nf = 0; nf < 8; nf++)
#pragma unroll
            for (int i = 0; i < 4; i++) acc[mf][nf][i] = 0.0f;

    const int NT = K / BKT;

    auto issue = [&](int kt) {
        int buf = kt % STAGES;
        const float* Asrc = Ap + (size_t)kt * BKT;
        const float* Bsrc = Bp + (size_t)kt * BKT * N;
        float* Asm = smem + (size_t)buf * (ASZ + BSZ);
        float* Bsm = Asm + ASZ;
#pragma unroll
        for (int i = 0; i < 8; i++) {                    // A: 2048 float4
            int idx = tid + 256 * i;
            int m = idx >> 3, kq = (idx & 7) * 4;
            uint32_t d = (uint32_t)__cvta_generic_to_shared(Asm + m * SA + kq);
            asm volatile("cp.async.cg.shared.global [%0], [%1], 16;"
                         :: "r"(d), "l"(Asrc + (size_t)m * K + kq));
        }
#pragma unroll
        for (int i = 0; i < 4; i++) {                    // B: 1024 float4
            int idx = tid + 256 * i;
            int k = idx >> 5, n = (idx & 31) * 4;
            uint32_t d = (uint32_t)__cvta_generic_to_shared(Bsm + k * SB + n);
            asm volatile("cp.async.cg.shared.global [%0], [%1], 16;"
                         :: "r"(d), "l"(Bsrc + (size_t)k * N + n));
        }
        asm volatile("cp.async.commit_group;");
    };

    issue(0);
    if (NT > 1) issue(1);

#pragma unroll 1
    for (int kt = 0; kt < NT; kt++) {
        if (kt + 2 < NT) {
            issue(kt + 2);
            asm volatile("cp.async.wait_group 2;" ::: "memory");
        } else if (kt + 1 < NT) {
            asm volatile("cp.async.wait_group 1;" ::: "memory");
        } else {
            asm volatile("cp.async.wait_group 0;" ::: "memory");
        }
        __syncthreads();

        const float* Asb = smem + (size_t)(kt % STAGES) * (ASZ + BSZ);
        const float* Bsb = Asb + ASZ;

#pragma unroll
        for (int ks = 0; ks < 4; ks++) {
            uint32_t af[4][4];
            uint32_t bf[8][2];
            const int arow = mW + (lane >> 2);
            const int acol = ks * 8 + (lane & 3);
#pragma unroll
            for (int mf = 0; mf < 4; mf++) {
                const float* p = Asb + (size_t)(arow + mf * 16) * SA + acol;
                af[mf][0] = __float_as_uint(p[0]);
                af[mf][1] = __float_as_uint(p[8 * SA]);
                af[mf][2] = __float_as_uint(p[4]);
                af[mf][3] = __float_as_uint(p[8 * SA + 4]);
            }
            const int brow = ks * 8 + (lane & 3);
            const int bcol = nW + (lane >> 2);
#pragma unroll
            for (int nf = 0; nf < 8; nf++) {
                const float* p = Bsb + (size_t)brow * SB + bcol + nf * 8;
                bf[nf][0] = __float_as_uint(p[0]);
                bf[nf][1] = __float_as_uint(p[4 * SB]);
            }
#pragma unroll
            for (int mf = 0; mf < 4; mf++)
#pragma unroll
                for (int nf = 0; nf < 8; nf++)
                    mma_tf32(acc[mf][nf], af[mf], bf[nf]);
        }
        __syncthreads();
    }

    // --- epilogue (float2 vectorized stores) ---
    const int s0 = g_sel[0], s1 = g_sel[1];
    const int bNoff = blockIdx.x * BN;
    const float* bias1 = (MODE == 0) ? (b1v + (size_t)g_sel[kslot] * FDIM) : nullptr;
#pragma unroll
    for (int mf = 0; mf < 4; mf++) {
        int r0 = blockIdx.y * BM + mW + mf * 16 + (lane >> 2);
        int r1 = r0 + 8;
        float rwA0, rwA1, rwB0, rwB1;
        if (MODE == 0) {
            rwA0 = g_rw[r0 * 2 + kslot];
            rwB0 = g_rw[r1 * 2 + kslot];
            rwA1 = rwB1 = 0.0f;
        } else {
            rwA0 = g_rw[r0 * 2 + 0]; rwA1 = g_rw[r0 * 2 + 1];
            rwB0 = g_rw[r1 * 2 + 0]; rwB1 = g_rw[r1 * 2 + 1];
        }
#pragma unroll
        for (int nf = 0; nf < 8; nf++) {
            int c0 = bNoff + nW + nf * 8 + (lane & 3) * 2;
            float2* p0 = (float2*)(C + (size_t)r0 * ldc + c0);
            float2* p1 = (float2*)(C + (size_t)r1 * ldc + c0);
            if (MODE == 0) {
                float2 bv = *(const float2*)(bias1 + c0);
                float2 o0, o1;
                o0.x = to_tf32(rwA0 * gelu_tanh(acc[mf][nf][0] + bv.x));
                o0.y = to_tf32(rwA0 * gelu_tanh(acc[mf][nf][1] + bv.y));
                o1.x = to_tf32(rwB0 * gelu_tanh(acc[mf][nf][2] + bv.x));
                o1.y = to_tf32(rwB0 * gelu_tanh(acc[mf][nf][3] + bv.y));
                *p0 = o0;
                *p1 = o1;
            } else {
                float2 ba = *(const float2*)(b2v + (size_t)s0 * DDIM + c0);
                float2 bb = *(const float2*)(b2v + (size_t)s1 * DDIM + c0);
                float2 o0, o1;
                o0.x = acc[mf][nf][0] + rwA0 * ba.x + rwA1 * bb.x;
                o0.y = acc[mf][nf][1] + rwA0 * ba.y + rwA1 * bb.y;
                o1.x = acc[mf][nf][2] + rwB0 * ba.x + rwB1 * bb.x;
                o1.y = acc[mf][nf][3] + rwB0 * ba.y + rwB1 * bb.y;
                *p0 = o0;
                *p1 = o1;
            }
        }
    }
}

// ---------------------------------------------------------------------------
// Launch
// ---------------------------------------------------------------------------
extern "C" void kernel_launch(void* const* d_in, const int* in_sizes, int n_in,
                              void* d_out, int out_size) {
    (void)in_sizes; (void)n_in; (void)out_size;
    const float* x  = (const float*)d_in[0];  // [2,4096,2048]
    const float* gw = (const float*)d_in[1];  // [8,2048]
    const float* w1 = (const float*)d_in[2];  // [8,2048,8192]
    const float* b1 = (const float*)d_in[3];  // [8,8192]
    const float* w2 = (const float*)d_in[4];  // [8,8192,2048]
    const float* b2 = (const float*)d_in[5];  // [8,2048]
    float* out = (float*)d_out;               // [2,4096,2048]

    void* p;
    cudaGetSymbolAddress(&p, g_h);   float* h   = (float*)p;
    cudaGetSymbolAddress(&p, g_xr);  float* xr  = (float*)p;
    cudaGetSymbolAddress(&p, g_w1r); float* w1r = (float*)p;
    cudaGetSymbolAddress(&p, g_w2r); float* w2r = (float*)p;

    cudaFuncSetAttribute(gemm_tf32<0>, cudaFuncAttributeMaxDynamicSharedMemorySize, GEMM_SMEM);
    cudaFuncSetAttribute(gemm_tf32<1>, cudaFuncAttributeMaxDynamicSharedMemorySize, GEMM_SMEM);

    // Routing (exact fp32)
    router_kernel<<<NTOK / 8, 256>>>(x, gw);
    colsum_kernel<<<ENUM, 256>>>();
    select_kernel<<<1, 1>>>();
    rw_kernel<<<NTOK / 256, 256>>>();

    // Round operands to tf32 (rna)
    const size_t perW = (size_t)DDIM * FDIM;
    const int n4x = NTOK * DDIM / 4;
    const int n4w = (int)(perW / 4);
    round_copy<<<(n4x + 255) / 256, 256>>>(x, xr, n4x);
    round_expert<<<(n4w + 255) / 256, 256>>>(w1, w1r,        perW, 0, n4w);
    round_expert<<<(n4w + 255) / 256, 256>>>(w1, w1r + perW, perW, 1, n4w);
    round_expert<<<(n4w + 255) / 256, 256>>>(w2, w2r,        perW, 0, n4w);
    round_expert<<<(n4w + 255) / 256, 256>>>(w2, w2r + perW, perW, 1, n4w);

    // GEMM1 (x2 experts): h[:, k*F : (k+1)*F] = to_tf32(rw[:,k] * gelu(x @ w1[sel_k] + b1[sel_k]))
    dim3 g1(FDIM / BN, NTOK / BM);
    gemm_tf32<0><<<g1, 256, GEMM_SMEM>>>(xr, w1r,        b1, nullptr, h,
                                         FDIM, DDIM, 2 * FDIM, 0);
    gemm_tf32<0><<<g1, 256, GEMM_SMEM>>>(xr, w1r + perW, b1, nullptr, h + FDIM,
                                         FDIM, DDIM, 2 * FDIM, 1);

    // GEMM2 (single fused K=16384): out = h @ [w2[s0]; w2[s1]] + rw0*b2[s0] + rw1*b2[s1]
    dim3 g2(DDIM / BN, NTOK / BM);
    gemm_tf32<1><<<g2, 256, GEMM_SMEM>>>(h, w2r, nullptr, b2, out,
                                         DDIM, 2 * FDIM, DDIM, 0);
}